// round 1
// baseline (speedup 1.0000x reference)
#include <cuda_runtime.h>
#include <cuda_bf16.h>

// Problem constants (fixed by setup_inputs)
#define B_ROWS 8192
#define N_NODES 2048
#define DIM 128
#define LEAKY 0.2f

// Scratch (no allocation allowed in kernel_launch)
__device__ float g_pscore[B_ROWS];
__device__ float g_nscore[N_NODES];
__device__ float g_nmax;

__device__ __forceinline__ float lrelu(float x) {
    return x > 0.0f ? x : LEAKY * x;
}

// ---------------------------------------------------------------------------
// Kernel 1: per-row dot products with attention kernel halves.
// One warp per row (patient rows then node rows). D=128 -> 32 float4 per row.
// ---------------------------------------------------------------------------
__global__ void score_kernel(const float* __restrict__ pf,
                             const float* __restrict__ dn,
                             const float* __restrict__ ak) {
    int gwarp = (blockIdx.x * blockDim.x + threadIdx.x) >> 5;
    int lane  = threadIdx.x & 31;
    if (gwarp < B_ROWS) {
        const float4 r = ((const float4*)(pf + (size_t)gwarp * DIM))[lane];
        const float4 a = ((const float4*)ak)[lane];            // a_p = ak[0:128]
        float s = r.x * a.x + r.y * a.y + r.z * a.z + r.w * a.w;
        #pragma unroll
        for (int o = 16; o > 0; o >>= 1) s += __shfl_xor_sync(0xffffffffu, s, o);
        if (lane == 0) g_pscore[gwarp] = s;
    } else if (gwarp < B_ROWS + N_NODES) {
        int j = gwarp - B_ROWS;
        const float4 r = ((const float4*)(dn + (size_t)j * DIM))[lane];
        const float4 a = ((const float4*)(ak + DIM))[lane];    // a_n = ak[128:256]
        float s = r.x * a.x + r.y * a.y + r.z * a.z + r.w * a.w;
        #pragma unroll
        for (int o = 16; o > 0; o >>= 1) s += __shfl_xor_sync(0xffffffffu, s, o);
        if (lane == 0) g_nscore[j] = s;
    }
}

// ---------------------------------------------------------------------------
// Kernel 2: global max of n_score (N=2048 -> 1 block of 1024 threads).
// ---------------------------------------------------------------------------
__global__ void nmax_kernel() {
    __shared__ float sm[1024];
    int tid = threadIdx.x;
    float v = fmaxf(g_nscore[tid], g_nscore[tid + 1024]);
    sm[tid] = v;
    __syncthreads();
    #pragma unroll
    for (int s = 512; s > 0; s >>= 1) {
        if (tid < s) sm[tid] = fmaxf(sm[tid], sm[tid + s]);
        __syncthreads();
    }
    if (tid == 0) g_nmax = sm[0];
}

// ---------------------------------------------------------------------------
// Kernel 3: main. out[b,:] = pf[b,:] + (1/Z_b) * sum_j e[b,j] * dn[j,:]
//   e[b,j] = exp(lrelu(ps_b + ns_j) - m_b),  m_b = lrelu(ps_b + n_max)
// Block: 256 threads = 8 warps. Each warp owns 4 rows. TB = 32 rows/block.
// j staged in smem tiles of TJ=64 (32 KB). e-tile stored as float4 (4 rows)
// per jj so the inner loop is 2 broadcast LDS.128 + 16 FFMA per jj.
// ---------------------------------------------------------------------------
constexpr int TJ = 64;
constexpr int TB = 32;
constexpr int MAIN_THREADS = 256;

__global__ __launch_bounds__(MAIN_THREADS)
void gat_main_kernel(const float* __restrict__ pf,
                     const float* __restrict__ dn,
                     float* __restrict__ out) {
    __shared__ float4 node_sm[TJ][DIM / 4];   // 32 KB
    __shared__ float  ns_sm[TJ];
    __shared__ float4 e_sm[8][TJ];            // [warp][jj] -> e for warp's 4 rows (8 KB)

    const int tid  = threadIdx.x;
    const int w    = tid >> 5;
    const int lane = tid & 31;
    const int row0 = blockIdx.x * TB + w * 4;

    const float nmax = g_nmax;

    float ps[4], m[4], denom[4];
    float4 acc[4];
    #pragma unroll
    for (int r = 0; r < 4; r++) {
        ps[r] = g_pscore[row0 + r];
        m[r]  = lrelu(ps[r] + nmax);
        denom[r] = 0.0f;
        acc[r] = make_float4(0.f, 0.f, 0.f, 0.f);
    }

    for (int jt = 0; jt < N_NODES; jt += TJ) {
        __syncthreads();
        // Stage node tile: TJ*DIM floats = 2048 float4, 8 per thread.
        const float4* src = (const float4*)(dn + (size_t)jt * DIM);
        #pragma unroll
        for (int i = 0; i < (TJ * DIM / 4) / MAIN_THREADS; i++) {
            int idx = tid + i * MAIN_THREADS;
            ((float4*)node_sm)[idx] = src[idx];
        }
        if (tid < TJ) ns_sm[tid] = g_nscore[jt + tid];
        __syncthreads();

        // e-tile for this warp's 4 rows: each lane computes 2 jj columns.
        #pragma unroll
        for (int h = 0; h < 2; h++) {
            int jj = lane + h * 32;
            float nsv = ns_sm[jj];
            float4 e;
            float* ep = &e.x;
            #pragma unroll
            for (int r = 0; r < 4; r++) {
                float x  = lrelu(ps[r] + nsv);
                float ev = __expf(x - m[r]);
                ep[r] = ev;
                denom[r] += ev;    // lane-partial; reduced after main loop
            }
            e_sm[w][jj] = e;
        }
        __syncwarp();

        // Accumulate: per jj, broadcast e (float4 = 4 rows) and node float4.
        #pragma unroll 16
        for (int jj = 0; jj < TJ; jj++) {
            float4 e = e_sm[w][jj];
            float4 v = node_sm[jj][lane];
            acc[0].x += e.x * v.x; acc[0].y += e.x * v.y; acc[0].z += e.x * v.z; acc[0].w += e.x * v.w;
            acc[1].x += e.y * v.x; acc[1].y += e.y * v.y; acc[1].z += e.y * v.z; acc[1].w += e.y * v.w;
            acc[2].x += e.z * v.x; acc[2].y += e.z * v.y; acc[2].z += e.z * v.z; acc[2].w += e.z * v.w;
            acc[3].x += e.w * v.x; acc[3].y += e.w * v.y; acc[3].z += e.w * v.z; acc[3].w += e.w * v.w;
        }
        __syncwarp();
    }

    // Reduce lane-partial denominators across the warp.
    #pragma unroll
    for (int r = 0; r < 4; r++) {
        float d = denom[r];
        #pragma unroll
        for (int o = 16; o > 0; o >>= 1) d += __shfl_xor_sync(0xffffffffu, d, o);
        denom[r] = d;
    }

    // Epilogue: out = pf + acc/denom
    #pragma unroll
    for (int r = 0; r < 4; r++) {
        float inv = 1.0f / denom[r];
        const float4 p = ((const float4*)(pf + (size_t)(row0 + r) * DIM))[lane];
        float4 o;
        o.x = p.x + acc[r].x * inv;
        o.y = p.y + acc[r].y * inv;
        o.z = p.z + acc[r].z * inv;
        o.w = p.w + acc[r].w * inv;
        ((float4*)(out + (size_t)(row0 + r) * DIM))[lane] = o;
    }
}

// ---------------------------------------------------------------------------
extern "C" void kernel_launch(void* const* d_in, const int* in_sizes, int n_in,
                              void* d_out, int out_size) {
    const float* pf = (const float*)d_in[0];   // patient_features [8192,128]
    const float* dn = (const float*)d_in[1];   // disease_nodes   [2048,128]
    const float* ak = (const float*)d_in[2];   // attn_kernel     [256,1]
    float* out = (float*)d_out;

    // 1) row scores: (B + N) warps, 8 warps/block
    int nwarps  = B_ROWS + N_NODES;
    int nblocks = (nwarps + 7) / 8;
    score_kernel<<<nblocks, 256>>>(pf, dn, ak);

    // 2) n_max
    nmax_kernel<<<1, 1024>>>();

    // 3) main
    gat_main_kernel<<<B_ROWS / TB, MAIN_THREADS>>>(pf, dn, out);
}

// round 5
// speedup vs baseline: 2.1739x; 2.1739x over previous
#include <cuda_runtime.h>
#include <cuda_bf16.h>
#include <cstdint>

#define B_ROWS 8192
#define N_NODES 2048
#define DIM 128
#define KTILE 64
#define NTILES (N_NODES / KTILE)     // 32
#define BLK_M 64
#define NBLK (B_ROWS / BLK_M)        // 128

// ---------------- scratch ----------------
__device__ float    g_nscore[N_NODES];
__device__ uint32_t g_nThi[NTILES * 4096];   // node^T bf16-hi, [tile][d=0..127][jpair=0..31]
__device__ uint32_t g_nTlo[NTILES * 4096];   // node^T bf16-lo

// stage layout (bytes), 144-byte row stride for conflict-free ldmatrix
#define ESTRIDE 144
#define NSTRIDE 144
#define EH_OFF 0
#define EL_OFF 9216
#define NH_OFF 18432
#define NL_OFF 36864
#define STAGE  55296
#define SMEM_MAIN (2 * STAGE)

// ---------------- helpers ----------------
__device__ __forceinline__ uint32_t smem_u32(const void* p) {
    uint32_t a;
    asm("{ .reg .u64 t; cvta.to.shared.u64 t, %1; cvt.u32.u64 %0, t; }" : "=r"(a) : "l"(p));
    return a;
}
__device__ __forceinline__ void ldsm_x4(uint32_t* r, uint32_t addr) {
    asm volatile("ldmatrix.sync.aligned.m8n8.x4.shared.b16 {%0,%1,%2,%3}, [%4];"
                 : "=r"(r[0]), "=r"(r[1]), "=r"(r[2]), "=r"(r[3]) : "r"(addr));
}
__device__ __forceinline__ void mma_bf16(float* d, const uint32_t* a, const uint32_t* b) {
    asm volatile("mma.sync.aligned.m16n8k16.row.col.f32.bf16.bf16.f32 "
                 "{%0,%1,%2,%3}, {%4,%5,%6,%7}, {%8,%9}, {%0,%1,%2,%3};"
                 : "+f"(d[0]), "+f"(d[1]), "+f"(d[2]), "+f"(d[3])
                 : "r"(a[0]), "r"(a[1]), "r"(a[2]), "r"(a[3]), "r"(b[0]), "r"(b[1]));
}
__device__ __forceinline__ void sts_v4(uint32_t addr, uint32_t a, uint32_t b, uint32_t c, uint32_t d) {
    asm volatile("st.shared.v4.b32 [%0], {%1,%2,%3,%4};"
                 :: "r"(addr), "r"(a), "r"(b), "r"(c), "r"(d) : "memory");
}
__device__ __forceinline__ float ex2f(float x) {
    float y; asm("ex2.approx.ftz.f32 %0, %1;" : "=f"(y) : "f"(x)); return y;
}
// pack(a -> low bf16, b -> high bf16)
__device__ __forceinline__ uint32_t pack_bf16x2(float a, float b) {
    uint32_t r;
    asm("cvt.rn.satfinite.bf16x2.f32 %0, %1, %2;" : "=r"(r) : "f"(b), "f"(a));
    return r;
}
__device__ __forceinline__ float bf16lo_f(uint32_t h) { return __uint_as_float(h << 16); }
__device__ __forceinline__ float bf16hi_f(uint32_t h) { return __uint_as_float(h & 0xFFFF0000u); }

// ---------------------------------------------------------------------------
// Kernel 1: prep. 128 blocks x 16 nodes. Computes node scores and writes
// transposed bf16 hi/lo tiles: g_nT*[tile*4096 + d*32 + jpair].
// ---------------------------------------------------------------------------
__global__ __launch_bounds__(256) void prep_kernel(const float* __restrict__ dn,
                                                   const float* __restrict__ ak) {
    __shared__ float sm[16 * 129];
    const int b   = blockIdx.x;          // 0..127
    const int tid = threadIdx.x;
    const float* src = dn + (size_t)b * 16 * DIM;

    #pragma unroll
    for (int i = 0; i < 8; i++) {
        int idx = tid + i * 256;         // 16*128 = 2048
        int j = idx >> 7, d = idx & 127;
        sm[j * 129 + d] = src[idx];
    }
    __syncthreads();

    if (tid < 64) {                       // node scores: 4 threads per node
        int j = tid >> 2, q = tid & 3;
        float s = 0.f;
        #pragma unroll
        for (int i = 0; i < 32; i++) {
            int d = q * 32 + i;
            s += sm[j * 129 + d] * __ldg(ak + DIM + d);
        }
        s += __shfl_xor_sync(0xffffffffu, s, 1);
        s += __shfl_xor_sync(0xffffffffu, s, 2);
        if (q == 0) g_nscore[b * 16 + j] = s;
    }

    // transpose + split: 128 d x 8 jpairs = 1024 words
    const int tile = b >> 2, qq = b & 3;
    #pragma unroll
    for (int i = 0; i < 4; i++) {
        int W = tid + i * 256;
        int d = W >> 3, jpl = W & 7;
        float v0 = sm[(2 * jpl) * 129 + d];
        float v1 = sm[(2 * jpl + 1) * 129 + d];
        uint32_t h = pack_bf16x2(v0, v1);
        float l0 = v0 - bf16lo_f(h);
        float l1 = v1 - bf16hi_f(h);
        uint32_t l = pack_bf16x2(l0, l1);
        int o = tile * 4096 + d * 32 + qq * 8 + jpl;
        g_nThi[o] = h;
        g_nTlo[o] = l;
    }
}

// ---------------------------------------------------------------------------
// Kernel 2: main. 128 CTAs x 64 rows, full K=2048 via 32 tiles of 64 nodes.
// Double-buffered smem; mma.sync bf16 split-precision (EhNh + EhNl + ElNh).
// ---------------------------------------------------------------------------
__global__ __launch_bounds__(256, 1)
void gat_mma_kernel(const float* __restrict__ pf, const float* __restrict__ ak,
                    float* __restrict__ out) {
    extern __shared__ char smem[];
    const uint32_t sb = smem_u32(smem);
    __shared__ float den_sm[BLK_M];
    __shared__ float red_sm[8];

    const int tid  = threadIdx.x;
    const int wid  = tid >> 5;
    const int lane = tid & 31;
    const int rb   = blockIdx.x;
    const int m    = tid >> 2;           // fill-role: row 0..63
    const int q    = tid & 3;            // fill-role: k-quarter (16 nodes)

    // ---- patient score for row m (all 4 quad threads end with the value) ----
    float ps;
    {
        const float4* pr = (const float4*)(pf + (size_t)(rb * BLK_M + m) * DIM + q * 32);
        const float4* ar = (const float4*)(ak + q * 32);
        float s = 0.f;
        #pragma unroll
        for (int i = 0; i < 8; i++) {
            float4 a = pr[i], c = ar[i];
            s += a.x * c.x + a.y * c.y + a.z * c.z + a.w * c.w;
        }
        s += __shfl_xor_sync(0xffffffffu, s, 1);
        s += __shfl_xor_sync(0xffffffffu, s, 2);
        ps = s;
    }
    // ---- nmax ----
    float nmax;
    {
        float mx = -1e30f;
        for (int i = tid; i < N_NODES; i += 256) mx = fmaxf(mx, g_nscore[i]);
        #pragma unroll
        for (int o = 16; o; o >>= 1) mx = fmaxf(mx, __shfl_xor_sync(0xffffffffu, mx, o));
        if (lane == 0) red_sm[wid] = mx;
        __syncthreads();
        nmax = red_sm[0];
        #pragma unroll
        for (int i = 1; i < 8; i++) nmax = fmaxf(nmax, red_sm[i]);
    }
    const float L  = 1.4426950408889634f;
    float xm = ps + nmax;
    const float mL = fmaxf(xm, 0.2f * xm) * L;   // row max (lrelu monotone) * log2e

    // warp tile: wm in {0,32}, wn in {0,32,64,96}
    const int wm = (wid & 1) * 32;
    const int wn = (wid >> 1) * 32;

    float acc[2][4][4];
    #pragma unroll
    for (int a = 0; a < 2; a++)
        #pragma unroll
        for (int b2 = 0; b2 < 4; b2++)
            #pragma unroll
            for (int c = 0; c < 4; c++) acc[a][b2][c] = 0.f;

    float den = 0.f;

    // staging registers
    uint4 nhr[4], nlr[4];
    float4 ns4[4];

    // fragment address precompute
    const uint32_t arow  = lane & 15;
    const uint32_t acol8 = lane >> 4;
    const uint32_t a_base = (wm + arow) * ESTRIDE + acol8 * 16;
    const uint32_t bn     = wn + ((lane >> 4) & 1) * 8 + (lane & 7);
    const uint32_t bk8    = (lane >> 3) & 1;
    const uint32_t b_base = bn * NSTRIDE + bk8 * 16;

    // E store address pieces
    const uint32_t e_addr_local = (uint32_t)(m * ESTRIDE + q * 32);

    // ---- prologue: load tile 0, pack, store to stage 0 ----
    {
        const uint4* ph = (const uint4*)(g_nThi);
        const uint4* pl = (const uint4*)(g_nTlo);
        #pragma unroll
        for (int i = 0; i < 4; i++) { nhr[i] = ph[tid + i * 256]; nlr[i] = pl[tid + i * 256]; }
        const float4* nsp = (const float4*)(g_nscore + q * 16);
        #pragma unroll
        for (int i = 0; i < 4; i++) ns4[i] = nsp[i];

        uint32_t eh[8], el[8];
        #pragma unroll
        for (int i = 0; i < 4; i++) {
            float x0 = ps + ns4[i].x; x0 = fmaxf(x0, 0.2f * x0);
            float x1 = ps + ns4[i].y; x1 = fmaxf(x1, 0.2f * x1);
            float x2 = ps + ns4[i].z; x2 = fmaxf(x2, 0.2f * x2);
            float x3 = ps + ns4[i].w; x3 = fmaxf(x3, 0.2f * x3);
            float e0 = ex2f(fmaf(x0, L, -mL));
            float e1 = ex2f(fmaf(x1, L, -mL));
            float e2 = ex2f(fmaf(x2, L, -mL));
            float e3 = ex2f(fmaf(x3, L, -mL));
            den += (e0 + e1) + (e2 + e3);
            uint32_t h01 = pack_bf16x2(e0, e1), h23 = pack_bf16x2(e2, e3);
            el[2*i]   = pack_bf16x2(e0 - bf16lo_f(h01), e1 - bf16hi_f(h01));
            el[2*i+1] = pack_bf16x2(e2 - bf16lo_f(h23), e3 - bf16hi_f(h23));
            eh[2*i] = h01; eh[2*i+1] = h23;
        }
        uint32_t ea = sb + EH_OFF + e_addr_local;
        sts_v4(ea,      eh[0], eh[1], eh[2], eh[3]);
        sts_v4(ea + 16, eh[4], eh[5], eh[6], eh[7]);
        uint32_t la = sb + EL_OFF + e_addr_local;
        sts_v4(la,      el[0], el[1], el[2], el[3]);
        sts_v4(la + 16, el[4], el[5], el[6], el[7]);
        #pragma unroll
        for (int i = 0; i < 4; i++) {
            int idx = tid + i * 256;
            uint32_t na = (uint32_t)((idx >> 3) * NSTRIDE + (idx & 7) * 16);
            sts_v4(sb + NH_OFF + na, nhr[i].x, nhr[i].y, nhr[i].z, nhr[i].w);
            sts_v4(sb + NL_OFF + na, nlr[i].x, nlr[i].y, nlr[i].z, nlr[i].w);
        }
    }
    __syncthreads();

    // ---- main loop ----
    for (int t = 0; t < NTILES; t++) {
        const int s = t & 1;
        const uint32_t stg = sb + s * STAGE;
        const bool more = (t + 1 < NTILES);

        if (more) {   // issue LDGs for t+1 early; latency hides under mma
            const uint4* ph = (const uint4*)(g_nThi + (t + 1) * 4096);
            const uint4* pl = (const uint4*)(g_nTlo + (t + 1) * 4096);
            #pragma unroll
            for (int i = 0; i < 4; i++) { nhr[i] = ph[tid + i * 256]; nlr[i] = pl[tid + i * 256]; }
            const float4* nsp = (const float4*)(g_nscore + (t + 1) * KTILE + q * 16);
            #pragma unroll
            for (int i = 0; i < 4; i++) ns4[i] = nsp[i];
        }

        // ---- mma over stage s ----
        {
            const uint32_t aH = stg + EH_OFF + a_base;
            const uint32_t aL = stg + EL_OFF + a_base;
            const uint32_t bH = stg + NH_OFF + b_base;
            const uint32_t bL = stg + NL_OFF + b_base;
            #pragma unroll
            for (int ks = 0; ks < 4; ks++) {
                uint32_t ah[2][4], al[2][4], bh[2][4], bl[2][4];
                ldsm_x4(ah[0], aH + ks * 32);
                ldsm_x4(ah[1], aH + ks * 32 + 16 * ESTRIDE);
                ldsm_x4(al[0], aL + ks * 32);
                ldsm_x4(al[1], aL + ks * 32 + 16 * ESTRIDE);
                ldsm_x4(bh[0], bH + ks * 32);
                ldsm_x4(bh[1], bH + ks * 32 + 16 * NSTRIDE);
                ldsm_x4(bl[0], bL + ks * 32);
                ldsm_x4(bl[1], bL + ks * 32 + 16 * NSTRIDE);
                #pragma unroll
                for (int mi = 0; mi < 2; mi++)
                    #pragma unroll
                    for (int g = 0; g < 2; g++)
                        #pragma unroll
                        for (int h = 0; h < 2; h++) {
                            float* d = acc[mi][g * 2 + h];
                            mma_bf16(d, ah[mi], &bh[g][h * 2]);
                            mma_bf16(d, ah[mi], &bl[g][h * 2]);
                            mma_bf16(d, al[mi], &bh[g][h * 2]);
                        }
            }
        }

        if (more) {
            // pack t+1 (MUFU)
            uint32_t eh[8], el[8];
            #pragma unroll
            for (int i = 0; i < 4; i++) {
                float x0 = ps + ns4[i].x; x0 = fmaxf(x0, 0.2f * x0);
                float x1 = ps + ns4[i].y; x1 = fmaxf(x1, 0.2f * x1);
                float x2 = ps + ns4[i].z; x2 = fmaxf(x2, 0.2f * x2);
                float x3 = ps + ns4[i].w; x3 = fmaxf(x3, 0.2f * x3);
                float e0 = ex2f(fmaf(x0, L, -mL));
                float e1 = ex2f(fmaf(x1, L, -mL));
                float e2 = ex2f(fmaf(x2, L, -mL));
                float e3 = ex2f(fmaf(x3, L, -mL));
                den += (e0 + e1) + (e2 + e3);
                uint32_t h01 = pack_bf16x2(e0, e1), h23 = pack_bf16x2(e2, e3);
                el[2*i]   = pack_bf16x2(e0 - bf16lo_f(h01), e1 - bf16hi_f(h01));
                el[2*i+1] = pack_bf16x2(e2 - bf16lo_f(h23), e3 - bf16hi_f(h23));
                eh[2*i] = h01; eh[2*i+1] = h23;
            }
            __syncthreads();   // all warps done reading stage s^1 (from mma t-1)
            const uint32_t nstg = sb + (s ^ 1) * STAGE;
            uint32_t ea = nstg + EH_OFF + e_addr_local;
            sts_v4(ea,      eh[0], eh[1], eh[2], eh[3]);
            sts_v4(ea + 16, eh[4], eh[5], eh[6], eh[7]);
            uint32_t la = nstg + EL_OFF + e_addr_local;
            sts_v4(la,      el[0], el[1], el[2], el[3]);
            sts_v4(la + 16, el[4], el[5], el[6], el[7]);
            #pragma unroll
            for (int i = 0; i < 4; i++) {
                int idx = tid + i * 256;
                uint32_t na = (uint32_t)((idx >> 3) * NSTRIDE + (idx & 7) * 16);
                sts_v4(nstg + NH_OFF + na, nhr[i].x, nhr[i].y, nhr[i].z, nhr[i].w);
                sts_v4(nstg + NL_OFF + na, nlr[i].x, nlr[i].y, nlr[i].z, nlr[i].w);
            }
            __syncthreads();   // stores visible before mma(t+1)
        }
    }

    // ---- denominator reduce (quad -> full row) ----
    den += __shfl_xor_sync(0xffffffffu, den, 1);
    den += __shfl_xor_sync(0xffffffffu, den, 2);
    if (q == 0) den_sm[m] = den;
    __syncthreads();

    // ---- epilogue: out = pf + acc / den ----
    const int r0 = lane >> 2;
    const int c0 = (lane & 3) * 2;
    #pragma unroll
    for (int mi = 0; mi < 2; mi++) {
        #pragma unroll
        for (int nj = 0; nj < 4; nj++) {
            const int col = wn + nj * 8 + c0;
            #pragma unroll
            for (int hh = 0; hh < 2; hh++) {
                const int row = wm + mi * 16 + r0 + hh * 8;
                const float inv = 1.0f / den_sm[row];
                const size_t gi = (size_t)(rb * BLK_M + row) * DIM + col;
                float2 p = *(const float2*)(pf + gi);
                float2 o;
                o.x = fmaf(acc[mi][nj][hh * 2 + 0], inv, p.x);
                o.y = fmaf(acc[mi][nj][hh * 2 + 1], inv, p.y);
                *(float2*)(out + gi) = o;
            }
        }
    }
}

// ---------------------------------------------------------------------------
extern "C" void kernel_launch(void* const* d_in, const int* in_sizes, int n_in,
                              void* d_out, int out_size) {
    const float* pf = (const float*)d_in[0];   // patient_features [8192,128]
    const float* dn = (const float*)d_in[1];   // disease_nodes   [2048,128]
    const float* ak = (const float*)d_in[2];   // attn_kernel     [256,1]
    float* out = (float*)d_out;

    cudaFuncSetAttribute(gat_mma_kernel, cudaFuncAttributeMaxDynamicSharedMemorySize, SMEM_MAIN);

    prep_kernel<<<128, 256>>>(dn, ak);
    gat_mma_kernel<<<NBLK, 256, SMEM_MAIN>>>(pf, ak, out);
}

// round 6
// speedup vs baseline: 2.2410x; 1.0309x over previous
#include <cuda_runtime.h>
#include <cuda_bf16.h>
#include <cstdint>

#define B_ROWS 8192
#define N_NODES 2048
#define DIM 128
#define KTILE 64
#define NTILES (N_NODES / KTILE)     // 32
#define BLK_M 64
#define NBLK (B_ROWS / BLK_M)        // 128
#define NTHREADS 512

// ---------------- scratch ----------------
__device__ float    g_nscore[N_NODES];
__device__ uint32_t g_nThi[NTILES * 4096];   // node^T bf16-hi, [tile][d=0..127][jpair=0..31]
__device__ uint32_t g_nTlo[NTILES * 4096];   // node^T bf16-lo

// stage layout (bytes), 144-byte row stride for conflict-free ldmatrix
#define ESTRIDE 144
#define NSTRIDE 144
#define EH_OFF 0
#define EL_OFF 9216
#define NH_OFF 18432
#define NL_OFF 36864
#define STAGE  55296
#define SMEM_MAIN (2 * STAGE)

// ---------------- helpers ----------------
__device__ __forceinline__ uint32_t smem_u32(const void* p) {
    uint32_t a;
    asm("{ .reg .u64 t; cvta.to.shared.u64 t, %1; cvt.u32.u64 %0, t; }" : "=r"(a) : "l"(p));
    return a;
}
__device__ __forceinline__ void ldsm_x4(uint32_t* r, uint32_t addr) {
    asm volatile("ldmatrix.sync.aligned.m8n8.x4.shared.b16 {%0,%1,%2,%3}, [%4];"
                 : "=r"(r[0]), "=r"(r[1]), "=r"(r[2]), "=r"(r[3]) : "r"(addr));
}
__device__ __forceinline__ void mma_bf16(float* d, const uint32_t* a, const uint32_t* b) {
    asm volatile("mma.sync.aligned.m16n8k16.row.col.f32.bf16.bf16.f32 "
                 "{%0,%1,%2,%3}, {%4,%5,%6,%7}, {%8,%9}, {%0,%1,%2,%3};"
                 : "+f"(d[0]), "+f"(d[1]), "+f"(d[2]), "+f"(d[3])
                 : "r"(a[0]), "r"(a[1]), "r"(a[2]), "r"(a[3]), "r"(b[0]), "r"(b[1]));
}
__device__ __forceinline__ void sts_v4(uint32_t addr, uint32_t a, uint32_t b, uint32_t c, uint32_t d) {
    asm volatile("st.shared.v4.b32 [%0], {%1,%2,%3,%4};"
                 :: "r"(addr), "r"(a), "r"(b), "r"(c), "r"(d) : "memory");
}
__device__ __forceinline__ float ex2f(float x) {
    float y; asm("ex2.approx.ftz.f32 %0, %1;" : "=f"(y) : "f"(x)); return y;
}
// pack(a -> low bf16, b -> high bf16)
__device__ __forceinline__ uint32_t pack_bf16x2(float a, float b) {
    uint32_t r;
    asm("cvt.rn.satfinite.bf16x2.f32 %0, %1, %2;" : "=r"(r) : "f"(b), "f"(a));
    return r;
}
__device__ __forceinline__ float bf16lo_f(uint32_t h) { return __uint_as_float(h << 16); }
__device__ __forceinline__ float bf16hi_f(uint32_t h) { return __uint_as_float(h & 0xFFFF0000u); }

// ---------------------------------------------------------------------------
// Kernel 1: prep (unchanged from R5). Node scores + transposed bf16 hi/lo tiles.
// ---------------------------------------------------------------------------
__global__ __launch_bounds__(256) void prep_kernel(const float* __restrict__ dn,
                                                   const float* __restrict__ ak) {
    __shared__ float sm[16 * 129];
    const int b   = blockIdx.x;          // 0..127
    const int tid = threadIdx.x;
    const float* src = dn + (size_t)b * 16 * DIM;

    #pragma unroll
    for (int i = 0; i < 8; i++) {
        int idx = tid + i * 256;
        int j = idx >> 7, d = idx & 127;
        sm[j * 129 + d] = src[idx];
    }
    __syncthreads();

    if (tid < 64) {
        int j = tid >> 2, q = tid & 3;
        float s = 0.f;
        #pragma unroll
        for (int i = 0; i < 32; i++) {
            int d = q * 32 + i;
            s += sm[j * 129 + d] * __ldg(ak + DIM + d);
        }
        s += __shfl_xor_sync(0xffffffffu, s, 1);
        s += __shfl_xor_sync(0xffffffffu, s, 2);
        if (q == 0) g_nscore[b * 16 + j] = s;
    }

    const int tile = b >> 2, qq = b & 3;
    #pragma unroll
    for (int i = 0; i < 4; i++) {
        int W = tid + i * 256;
        int d = W >> 3, jpl = W & 7;
        float v0 = sm[(2 * jpl) * 129 + d];
        float v1 = sm[(2 * jpl + 1) * 129 + d];
        uint32_t h = pack_bf16x2(v0, v1);
        float l0 = v0 - bf16lo_f(h);
        float l1 = v1 - bf16hi_f(h);
        uint32_t l = pack_bf16x2(l0, l1);
        int o = tile * 4096 + d * 32 + qq * 8 + jpl;
        g_nThi[o] = h;
        g_nTlo[o] = l;
    }
}

// ---------------------------------------------------------------------------
// Kernel 2: main. 128 CTAs x 64 rows, 512 threads (16 warps).
// K-split across warp halves: warps 0-7 -> k[0:32), warps 8-15 -> k[32:64)
// of each 64-node tile; partial accs reduced via smem at the epilogue.
// ---------------------------------------------------------------------------
__global__ __launch_bounds__(NTHREADS, 1)
void gat_mma_kernel(const float* __restrict__ pf, const float* __restrict__ ak,
                    float* __restrict__ out) {
    extern __shared__ char smem[];
    const uint32_t sb = smem_u32(smem);
    __shared__ float den_sm[BLK_M];
    __shared__ float red_sm[16];

    const int tid  = threadIdx.x;
    const int wid  = tid >> 5;
    const int lane = tid & 31;
    const int rb   = blockIdx.x;
    // fill roles: row m (0..63), octant q (8 nodes each)
    const int m = tid >> 3;
    const int q = tid & 7;
    // mma roles
    const int wk = wid >> 3;           // k-half of each tile
    const int w8 = wid & 7;
    const int wm = (w8 & 1) * 32;
    const int wn = (w8 >> 1) * 32;

    // ---- patient score for row m (16 dims per thread, reduce over 8) ----
    float ps;
    {
        const float4* pr = (const float4*)(pf + (size_t)(rb * BLK_M + m) * DIM + q * 16);
        const float4* ar = (const float4*)(ak + q * 16);
        float s = 0.f;
        #pragma unroll
        for (int i = 0; i < 4; i++) {
            float4 a = pr[i], c = ar[i];
            s += a.x * c.x + a.y * c.y + a.z * c.z + a.w * c.w;
        }
        s += __shfl_xor_sync(0xffffffffu, s, 1);
        s += __shfl_xor_sync(0xffffffffu, s, 2);
        s += __shfl_xor_sync(0xffffffffu, s, 4);
        ps = s;
    }
    // ---- nmax ----
    float nmax;
    {
        float mx = -1e30f;
        #pragma unroll
        for (int i = 0; i < N_NODES / NTHREADS; i++) mx = fmaxf(mx, g_nscore[tid + i * NTHREADS]);
        #pragma unroll
        for (int o = 16; o; o >>= 1) mx = fmaxf(mx, __shfl_xor_sync(0xffffffffu, mx, o));
        if (lane == 0) red_sm[wid] = mx;
        __syncthreads();
        nmax = red_sm[0];
        #pragma unroll
        for (int i = 1; i < 16; i++) nmax = fmaxf(nmax, red_sm[i]);
    }
    const float L  = 1.4426950408889634f;
    float xm = ps + nmax;
    const float mL = fmaxf(xm, 0.2f * xm) * L;   // row max (lrelu monotone) * log2e

    float acc[2][4][4];
    #pragma unroll
    for (int a = 0; a < 2; a++)
        #pragma unroll
        for (int b2 = 0; b2 < 4; b2++)
            #pragma unroll
            for (int c = 0; c < 4; c++) acc[a][b2][c] = 0.f;

    float den = 0.f;

    // staging registers
    uint4 nhr[2], nlr[2];
    float4 ns4[2];

    // fragment addresses (k-block offset added per ks)
    const uint32_t arow  = lane & 15;
    const uint32_t acol8 = lane >> 4;
    const uint32_t a_base = (wm + arow) * ESTRIDE + acol8 * 16;
    const uint32_t bn     = wn + ((lane >> 4) & 1) * 8 + (lane & 7);
    const uint32_t bk8    = (lane >> 3) & 1;
    const uint32_t b_base = bn * NSTRIDE + bk8 * 16;
    const uint32_t kbase  = wk * 64;   // byte offset of this warp's k-half

    const uint32_t e_addr_local = (uint32_t)(m * ESTRIDE + q * 16);

    // ---- prologue: tile 0 -> stage 0 ----
    {
        const uint4* ph = (const uint4*)(g_nThi);
        const uint4* pl = (const uint4*)(g_nTlo);
        #pragma unroll
        for (int i = 0; i < 2; i++) { nhr[i] = ph[tid + i * NTHREADS]; nlr[i] = pl[tid + i * NTHREADS]; }
        const float4* nsp = (const float4*)(g_nscore + q * 8);
        ns4[0] = nsp[0]; ns4[1] = nsp[1];

        uint32_t eh[4], el[4];
        #pragma unroll
        for (int i = 0; i < 2; i++) {
            float x0 = ps + ns4[i].x; x0 = fmaxf(x0, 0.2f * x0);
            float x1 = ps + ns4[i].y; x1 = fmaxf(x1, 0.2f * x1);
            float x2 = ps + ns4[i].z; x2 = fmaxf(x2, 0.2f * x2);
            float x3 = ps + ns4[i].w; x3 = fmaxf(x3, 0.2f * x3);
            float e0 = ex2f(fmaf(x0, L, -mL));
            float e1 = ex2f(fmaf(x1, L, -mL));
            float e2 = ex2f(fmaf(x2, L, -mL));
            float e3 = ex2f(fmaf(x3, L, -mL));
            den += (e0 + e1) + (e2 + e3);
            uint32_t h01 = pack_bf16x2(e0, e1), h23 = pack_bf16x2(e2, e3);
            el[2*i]   = pack_bf16x2(e0 - bf16lo_f(h01), e1 - bf16hi_f(h01));
            el[2*i+1] = pack_bf16x2(e2 - bf16lo_f(h23), e3 - bf16hi_f(h23));
            eh[2*i] = h01; eh[2*i+1] = h23;
        }
        sts_v4(sb + EH_OFF + e_addr_local, eh[0], eh[1], eh[2], eh[3]);
        sts_v4(sb + EL_OFF + e_addr_local, el[0], el[1], el[2], el[3]);
        #pragma unroll
        for (int i = 0; i < 2; i++) {
            int idx = tid + i * NTHREADS;
            uint32_t na = (uint32_t)((idx >> 3) * NSTRIDE + (idx & 7) * 16);
            sts_v4(sb + NH_OFF + na, nhr[i].x, nhr[i].y, nhr[i].z, nhr[i].w);
            sts_v4(sb + NL_OFF + na, nlr[i].x, nlr[i].y, nlr[i].z, nlr[i].w);
        }
    }
    __syncthreads();

    // ---- main loop ----
    for (int t = 0; t < NTILES; t++) {
        const int s = t & 1;
        const uint32_t stg = sb + s * STAGE;
        const bool more = (t + 1 < NTILES);

        if (more) {   // issue LDGs for t+1 early; latency hides under mma
            const uint4* ph = (const uint4*)(g_nThi + (t + 1) * 4096);
            const uint4* pl = (const uint4*)(g_nTlo + (t + 1) * 4096);
            #pragma unroll
            for (int i = 0; i < 2; i++) { nhr[i] = ph[tid + i * NTHREADS]; nlr[i] = pl[tid + i * NTHREADS]; }
            const float4* nsp = (const float4*)(g_nscore + (t + 1) * KTILE + q * 8);
            ns4[0] = nsp[0]; ns4[1] = nsp[1];
        }

        // ---- mma over stage s, this warp's k-half (2 of 4 k16 blocks) ----
        {
            const uint32_t aH = stg + EH_OFF + a_base + kbase;
            const uint32_t aL = stg + EL_OFF + a_base + kbase;
            const uint32_t bH = stg + NH_OFF + b_base + kbase;
            const uint32_t bL = stg + NL_OFF + b_base + kbase;
            #pragma unroll
            for (int ks = 0; ks < 2; ks++) {
                uint32_t ah[2][4], al[2][4], bh[2][4], bl[2][4];
                ldsm_x4(ah[0], aH + ks * 32);
                ldsm_x4(ah[1], aH + ks * 32 + 16 * ESTRIDE);
                ldsm_x4(al[0], aL + ks * 32);
                ldsm_x4(al[1], aL + ks * 32 + 16 * ESTRIDE);
                ldsm_x4(bh[0], bH + ks * 32);
                ldsm_x4(bh[1], bH + ks * 32 + 16 * NSTRIDE);
                ldsm_x4(bl[0], bL + ks * 32);
                ldsm_x4(bl[1], bL + ks * 32 + 16 * NSTRIDE);
                #pragma unroll
                for (int mi = 0; mi < 2; mi++)
                    #pragma unroll
                    for (int g = 0; g < 2; g++)
                        #pragma unroll
                        for (int h = 0; h < 2; h++) {
                            float* d = acc[mi][g * 2 + h];
                            mma_bf16(d, ah[mi], &bh[g][h * 2]);
                            mma_bf16(d, ah[mi], &bl[g][h * 2]);
                            mma_bf16(d, al[mi], &bh[g][h * 2]);
                        }
            }
        }

        if (more) {
            // pack t+1
            uint32_t eh[4], el[4];
            #pragma unroll
            for (int i = 0; i < 2; i++) {
                float x0 = ps + ns4[i].x; x0 = fmaxf(x0, 0.2f * x0);
                float x1 = ps + ns4[i].y; x1 = fmaxf(x1, 0.2f * x1);
                float x2 = ps + ns4[i].z; x2 = fmaxf(x2, 0.2f * x2);
                float x3 = ps + ns4[i].w; x3 = fmaxf(x3, 0.2f * x3);
                float e0 = ex2f(fmaf(x0, L, -mL));
                float e1 = ex2f(fmaf(x1, L, -mL));
                float e2 = ex2f(fmaf(x2, L, -mL));
                float e3 = ex2f(fmaf(x3, L, -mL));
                den += (e0 + e1) + (e2 + e3);
                uint32_t h01 = pack_bf16x2(e0, e1), h23 = pack_bf16x2(e2, e3);
                el[2*i]   = pack_bf16x2(e0 - bf16lo_f(h01), e1 - bf16hi_f(h01));
                el[2*i+1] = pack_bf16x2(e2 - bf16lo_f(h23), e3 - bf16hi_f(h23));
                eh[2*i] = h01; eh[2*i+1] = h23;
            }
            __syncthreads();   // all warps done reading stage s^1
            const uint32_t nstg = sb + (s ^ 1) * STAGE;
            sts_v4(nstg + EH_OFF + e_addr_local, eh[0], eh[1], eh[2], eh[3]);
            sts_v4(nstg + EL_OFF + e_addr_local, el[0], el[1], el[2], el[3]);
            #pragma unroll
            for (int i = 0; i < 2; i++) {
                int idx = tid + i * NTHREADS;
                uint32_t na = (uint32_t)((idx >> 3) * NSTRIDE + (idx & 7) * 16);
                sts_v4(nstg + NH_OFF + na, nhr[i].x, nhr[i].y, nhr[i].z, nhr[i].w);
                sts_v4(nstg + NL_OFF + na, nlr[i].x, nlr[i].y, nlr[i].z, nlr[i].w);
            }
            __syncthreads();   // stores visible before mma(t+1)
        }
    }

    // ---- denominator reduce (8 q-threads per row) ----
    den += __shfl_xor_sync(0xffffffffu, den, 1);
    den += __shfl_xor_sync(0xffffffffu, den, 2);
    den += __shfl_xor_sync(0xffffffffu, den, 4);
    if (q == 0) den_sm[m] = den;

    __syncthreads();   // all mma done -> safe to reuse dynamic smem; den_sm visible

    // ---- k-split reduce via smem (stride 36 floats to dodge conflicts) ----
    float* red = (float*)smem;
    const int rbase = (w8 * 32 + lane) * 36;
    if (wk == 1) {
        #pragma unroll
        for (int mi = 0; mi < 2; mi++)
            #pragma unroll
            for (int nj = 0; nj < 4; nj++)
                *(float4*)(red + rbase + mi * 16 + nj * 4) =
                    make_float4(acc[mi][nj][0], acc[mi][nj][1], acc[mi][nj][2], acc[mi][nj][3]);
    }
    __syncthreads();

    if (wk == 0) {
        #pragma unroll
        for (int mi = 0; mi < 2; mi++)
            #pragma unroll
            for (int nj = 0; nj < 4; nj++) {
                float4 v = *(const float4*)(red + rbase + mi * 16 + nj * 4);
                acc[mi][nj][0] += v.x; acc[mi][nj][1] += v.y;
                acc[mi][nj][2] += v.z; acc[mi][nj][3] += v.w;
            }

        // ---- epilogue: out = pf + acc / den ----
        const int r0 = lane >> 2;
        const int c0 = (lane & 3) * 2;
        #pragma unroll
        for (int mi = 0; mi < 2; mi++) {
            #pragma unroll
            for (int nj = 0; nj < 4; nj++) {
                const int col = wn + nj * 8 + c0;
                #pragma unroll
                for (int hh = 0; hh < 2; hh++) {
                    const int row = wm + mi * 16 + r0 + hh * 8;
                    const float inv = 1.0f / den_sm[row];
                    const size_t gi = (size_t)(rb * BLK_M + row) * DIM + col;
                    float2 p = *(const float2*)(pf + gi);
                    float2 o;
                    o.x = fmaf(acc[mi][nj][hh * 2 + 0], inv, p.x);
                    o.y = fmaf(acc[mi][nj][hh * 2 + 1], inv, p.y);
                    *(float2*)(out + gi) = o;
                }
            }
        }
    }
}

// ---------------------------------------------------------------------------
extern "C" void kernel_launch(void* const* d_in, const int* in_sizes, int n_in,
                              void* d_out, int out_size) {
    const float* pf = (const float*)d_in[0];   // patient_features [8192,128]
    const float* dn = (const float*)d_in[1];   // disease_nodes   [2048,128]
    const float* ak = (const float*)d_in[2];   // attn_kernel     [256,1]
    float* out = (float*)d_out;

    cudaFuncSetAttribute(gat_mma_kernel, cudaFuncAttributeMaxDynamicSharedMemorySize, SMEM_MAIN);

    prep_kernel<<<128, 256>>>(dn, ak);
    gat_mma_kernel<<<NBLK, NTHREADS, SMEM_MAIN>>>(pf, ak, out);
}